// round 9
// baseline (speedup 1.0000x reference)
#include <cuda_runtime.h>
#include <cstdint>

#define D    512
#define NBAT 256
#define H    128
#define LDIM 64
#define NV   32000
#define G5   640          // 5*H
#define NH   (NBAT*H)     // 32768

// ---- persistent device scratch (allocation-free rule) ----
__device__ float g_hst[D * NBAT * H];     // 64 MB
__device__ float g_cst[D * NBAT * H];     // 64 MB
__device__ float g_table[(size_t)NV * G5];// 82 MB: emb@W[0:64] + b
__device__ int   g_lidx[D * NBAT];        // left-child step index, -1 = shift

__device__ __forceinline__ float sigf(float x) {
    return __fdividef(1.0f, 1.0f + __expf(-x));
}
__device__ __forceinline__ float tanhfast(float x) {
    return 1.0f - __fdividef(2.0f, __expf(2.0f * x) + 1.0f);
}
__device__ __forceinline__ float ull_lo(unsigned long long v) {
    return __uint_as_float((unsigned)(v & 0xffffffffull));
}
__device__ __forceinline__ float ull_hi(unsigned long long v) {
    return __uint_as_float((unsigned)(v >> 32));
}

// ============================================================
// K_pre: grid (1000, 5). y<4: table tiles; y==4,x==0: lidx sim.
// ============================================================
__global__ __launch_bounds__(256) void k_pre(const float* __restrict__ emb,
                                             const float* __restrict__ W,
                                             const float* __restrict__ bias,
                                             const int* __restrict__ trans) {
    if (blockIdx.y == 4) {
        if (blockIdx.x != 0) return;
        int b = threadIdx.x;
        short st[D];
        int ptr = 0;
        for (int t = 0; t < D; t++) {
            int m = trans[t * NBAT + b];
            int lx = -1;
            if (m) lx = st[ptr - 2];
            int np = ptr - 2 * m;
            st[np] = (short)t;
            ptr = np + 1;
            g_lidx[t * NBAT + b] = lx;
        }
        return;
    }
    extern __shared__ float sm[];
    float* emb_s = sm;              // [64][33]
    float* W_sc  = sm + 64 * 33;    // [64][160]
    const int v0 = blockIdx.x * 32;
    const int c0 = blockIdx.y * 160;
    const int tid = threadIdx.x;

    for (int idx = tid; idx < 32 * 64; idx += 256) {
        int vv = idx >> 6, k = idx & 63;
        emb_s[k * 33 + vv] = emb[(v0 + vv) * LDIM + k];
    }
    for (int idx = tid; idx < 64 * 40; idx += 256) {
        int k = idx / 40, cq = idx % 40;
        float4 w4 = *reinterpret_cast<const float4*>(&W[k * G5 + c0 + cq * 4]);
        *reinterpret_cast<float4*>(&W_sc[k * 160 + cq * 4]) = w4;
    }
    __syncthreads();

    const int vg = tid & 7;
    const int cg = tid >> 3;
    float acc[4][5];
#pragma unroll
    for (int j = 0; j < 5; j++) {
        float bj = __ldg(&bias[c0 + cg * 5 + j]);
#pragma unroll
        for (int i = 0; i < 4; i++) acc[i][j] = bj;
    }
#pragma unroll 4
    for (int k = 0; k < 64; k++) {
        float x[4], w[5];
#pragma unroll
        for (int i = 0; i < 4; i++) x[i] = emb_s[k * 33 + vg * 4 + i];
#pragma unroll
        for (int j = 0; j < 5; j++) w[j] = W_sc[k * 160 + cg * 5 + j];
#pragma unroll
        for (int i = 0; i < 4; i++)
#pragma unroll
            for (int j = 0; j < 5; j++) acc[i][j] += x[i] * w[j];
    }
#pragma unroll
    for (int i = 0; i < 4; i++)
#pragma unroll
        for (int j = 0; j < 5; j++)
            g_table[(size_t)(v0 + vg * 4 + i) * G5 + c0 + cg * 5 + j] = acc[i][j];
}

// ============================================================
// Main: 32 active clusters of 4 CTAs (grid 148, 5 dummy clusters).
// Cluster owns 8 batch; CTA rank r owns hdims [32r, 32r+32).
// R9: coalesced v4 DSMEM push (1 store/thread), writeback before arrive.
// ============================================================
#define XK     260
#define WROW   260
#define XBUF   (8 * XK)                      // 2080 floats
#define HSROW  36
#define SM_WT  0                             // 160*260 = 41600
#define SM_X   41600                         // 2*2080 = 4160
#define SM_LF  45760                         // 128
#define SM_HS  45888                         // 8*36 = 288
#define SM_CS  46176                         // 288
#define SM_MB  46464                         // 8B aligned
#define SM_TOT ((46466) * 4)

__global__ __launch_bounds__(256, 1) __cluster_dims__(4, 1, 1)
void k_main(const int* __restrict__ labels,
            const float* __restrict__ W,
            const float* __restrict__ leaf,
            float* __restrict__ out) {
    const int bx = blockIdx.x;
    if ((bx >> 2) >= 32) return;   // dummy clusters

    extern __shared__ float sm[];
    float* W_T    = sm + SM_WT;    // [160][260]
    float* Xbuf   = sm + SM_X;     // 2 x [8][260]
    float* leaf_s = sm + SM_LF;
    float* hstage = sm + SM_HS;    // [8][36]
    float* cstage = sm + SM_CS;

    const int r   = bx & 3;
    const int B   = (bx >> 2) * 8;
    const int tid = threadIdx.x;
    const int r32 = r * 32;
    const uint32_t mb = (uint32_t)__cvta_generic_to_shared(sm + SM_MB);
    const uint32_t xbase = (uint32_t)__cvta_generic_to_shared(Xbuf);

    // roles
    const int b   = tid & 7;       // GEMM/nonlin batch
    const int jj  = tid >> 3;      // hdim within slice (0..31)
    const int b2  = tid >> 5;      // cp.async / writeback batch
    const int s2  = tid & 31;      // segment / hdim col
    // push roles: one float4 per thread
    const int ptgt = tid >> 6;     // target CTA 0..3
    const int pb   = (tid & 63) >> 3;   // batch 0..7
    const int pc   = tid & 7;           // float4 chunk 0..7 (32 hdims)

    // ---- prologue: W_T[c][k] ----
    for (int k = 0; k < 256; k++) {
        if (tid < 160) {
            int g = tid >> 5, cc = tid & 31;
            W_T[tid * WROW + k] = __ldg(&W[(64 + k) * G5 + g * H + r32 + cc]);
        }
    }
    if (tid < 128) leaf_s[tid] = leaf[tid];
    if (tid == 0)
        asm volatile("mbarrier.init.shared.b64 [%0], %1;" :: "r"(mb), "r"(4) : "memory");
    __syncthreads();
    asm volatile("barrier.cluster.arrive.aligned;" ::: "memory");
    asm volatile("barrier.cluster.wait.aligned;" ::: "memory");

    // leafW
    float lw5[5];
#pragma unroll
    for (int g = 0; g < 5; g++) lw5[g] = 0.0f;
    for (int k = 0; k < 128; k++) {
        float lv = leaf_s[k];
#pragma unroll
        for (int g = 0; g < 5; g++)
            lw5[g] += lv * (W_T[(g * 32 + jj) * WROW + k]
                          + W_T[(g * 32 + jj) * WROW + 128 + k]);
    }

    // schedule regs
    int liA  = __ldg(&g_lidx[B + b]);
    int liB  = __ldg(&g_lidx[NBAT + B + b]);
    int labB = __ldg(&labels[NBAT + B + b]);
    float tab5[5];
    {
        int labA = __ldg(&labels[B + b]);
#pragma unroll
        for (int g = 0; g < 5; g++)
            tab5[g] = __ldg(&g_table[(size_t)labA * G5 + g * H + r32 + jj]);
    }
    float cl = leaf_s[r32 + jj];
    float cprev = 0.0f;
    int cur = 0;

    for (int t = 0; t < D; t++) {
        __syncthreads();   // X[cur] complete
        float* Xc = Xbuf + cur * XBUF;
        const int nxt = cur ^ 1;

        float cln = 0.0f, t5n[5];
        int liC = 0, labC = 0;
        if (t < D - 1) {
            bool redB = (liB >= 0);
            cln = redB
                ? ((liB == t - 1) ? cprev
                   : __ldcg(&g_cst[(size_t)liB * NH + (B + b) * H + r32 + jj]))
                : leaf_s[r32 + jj];
#pragma unroll
            for (int g = 0; g < 5; g++)
                t5n[g] = __ldg(&g_table[(size_t)labB * G5 + g * H + r32 + jj]);
            const int t2 = (t + 2 < D) ? (t + 2) : (D - 1);
            liC  = __ldg(&g_lidx[t2 * NBAT + B + b]);
            labC = __ldg(&labels[t2 * NBAT + B + b]);

            // left-half X[next]
            int li2 = __ldg(&g_lidx[(t + 1) * NBAT + B + b2]);
            if (li2 >= 0) {
                uint32_t dst = xbase + (nxt * XBUF + b2 * XK + s2 * 4) * 4;
                if (li2 == t - 1) {
                    float4 v = *reinterpret_cast<const float4*>(
                        &Xc[b2 * XK + 128 + s2 * 4]);
                    *reinterpret_cast<float4*>(
                        &Xbuf[nxt * XBUF + b2 * XK + s2 * 4]) = v;
                } else {
                    const float* src = &g_hst[(size_t)li2 * NH + (B + b2) * H + s2 * 4];
                    asm volatile("cp.async.cg.shared.global [%0], [%1], 16;"
                                 :: "r"(dst), "l"(src) : "memory");
                }
            }
            asm volatile("cp.async.commit_group;" ::: "memory");
        }

        // ---- GEMM over full K=256 (f32x2) ----
        unsigned long long acc[5];
#pragma unroll
        for (int g = 0; g < 5; g++) acc[g] = 0ULL;
        {
            const ulonglong2* xp = reinterpret_cast<const ulonglong2*>(Xc + b * XK);
            const ulonglong2* wp =
                reinterpret_cast<const ulonglong2*>(W_T + jj * WROW);
#pragma unroll 8
            for (int p = 0; p < 64; p++) {
                ulonglong2 xv = xp[p];
#pragma unroll
                for (int g = 0; g < 5; g++) {
                    ulonglong2 wv = wp[p + g * 2080];
                    asm("fma.rn.f32x2 %0, %1, %2, %0;"
                        : "+l"(acc[g]) : "l"(xv.x), "l"(wv.x));
                    asm("fma.rn.f32x2 %0, %1, %2, %0;"
                        : "+l"(acc[g]) : "l"(xv.y), "l"(wv.y));
                }
            }
        }

        // ---- nonlinearity -> stage ----
        {
            float gate[5];
            if (liA >= 0) {
#pragma unroll
                for (int g = 0; g < 5; g++)
                    gate[g] = tab5[g] + ull_lo(acc[g]) + ull_hi(acc[g]);
            } else {
#pragma unroll
                for (int g = 0; g < 5; g++) gate[g] = tab5[g] + lw5[g];
            }
            float lf  = leaf_s[r32 + jj];
            float clv = (liA >= 0) ? cl    : lf;
            float crv = (liA >= 0) ? cprev : lf;
            float c = sigf(gate[0]) * tanhfast(gate[4])
                    + sigf(gate[1]) * clv + sigf(gate[2]) * crv;
            float h = sigf(gate[3]) * tanhfast(c);
            cprev = c;
            hstage[b * HSROW + jj] = h;
            cstage[b * HSROW + jj] = c;
        }
        __syncthreads();   // stage complete

        // ---- coalesced v4 push: one st per thread ----
        if (t < D - 1) {
            float4 v = *reinterpret_cast<const float4*>(&hstage[pb * HSROW + pc * 4]);
            uint32_t xaddr = xbase + (nxt * XBUF + pb * XK + 128 + r32 + pc * 4) * 4;
            if (ptgt == r) {
                *reinterpret_cast<float4*>(
                    &Xbuf[nxt * XBUF + pb * XK + 128 + r32 + pc * 4]) = v;
            } else {
                uint32_t rem;
                asm("mapa.shared::cluster.u32 %0, %1, %2;"
                    : "=r"(rem) : "r"(xaddr), "r"(ptgt));
                asm volatile("st.shared::cluster.v4.f32 [%0], {%1, %2, %3, %4};"
                             :: "r"(rem), "f"(v.x), "f"(v.y), "f"(v.z), "f"(v.w)
                             : "memory");
            }
        }
        // ---- writeback BEFORE arrive (release orders it for consumers) ----
        {
            float hv = hstage[b2 * HSROW + s2];
            float cv = cstage[b2 * HSROW + s2];
            const size_t o = (size_t)t * NH + (B + b2) * H + r32 + s2;
            __stcg(&g_hst[o], hv);
            __stcg(&g_cst[o], cv);
            if (t == D - 1) {
                out[(B + b2) * H + r32 + s2]      = cv;   // cells
                out[NH + (B + b2) * H + r32 + s2] = hv;   // embeddings
            }
        }
        __syncthreads();   // pushes + writeback issued CTA-wide

        // ---- handshake ----
        if (t < D - 1) {
            if (tid < 4) {
                uint32_t rem;
                asm("mapa.shared::cluster.u32 %0, %1, %2;"
                    : "=r"(rem) : "r"(mb), "r"(tid));
                asm volatile("mbarrier.arrive.release.cluster.shared::cluster.b64 _, [%0];"
                             :: "r"(rem) : "memory");
            }
            const unsigned par = t & 1;
            asm volatile(
                "{\n\t"
                ".reg .pred P;\n\t"
                "WL%=:\n\t"
                "mbarrier.try_wait.parity.acquire.cluster.shared::cta.b64 P, [%0], %1, 0x989680;\n\t"
                "@P bra WD%=;\n\t"
                "bra WL%=;\n\t"
                "WD%=:\n\t"
                "}" :: "r"(mb), "r"(par) : "memory");
            asm volatile("cp.async.wait_group 0;" ::: "memory");
        }

        liA = liB; liB = liC; labB = labC;
        cl = cln;
#pragma unroll
        for (int g = 0; g < 5; g++) tab5[g] = t5n[g];
        cur ^= 1;
    }

    asm volatile("barrier.cluster.arrive.aligned;" ::: "memory");
    asm volatile("barrier.cluster.wait.aligned;" ::: "memory");
}

// ============================================================
extern "C" void kernel_launch(void* const* d_in, const int* in_sizes, int n_in,
                              void* d_out, int out_size) {
    const int*   trans  = (const int*)d_in[0];
    const int*   labels = (const int*)d_in[1];
    const float* emb    = (const float*)d_in[2];
    const float* W      = (const float*)d_in[3];
    const float* bias   = (const float*)d_in[4];
    const float* leaf   = (const float*)d_in[5];
    float* out = (float*)d_out;

    cudaFuncSetAttribute(k_pre, cudaFuncAttributeMaxDynamicSharedMemorySize,
                         64 * 33 * 4 + 64 * 160 * 4);
    cudaFuncSetAttribute(k_main, cudaFuncAttributeMaxDynamicSharedMemorySize,
                         SM_TOT);

    dim3 pgrid(NV / 32, 5);
    k_pre<<<pgrid, 256, 64 * 33 * 4 + 64 * 160 * 4>>>(emb, W, bias, trans);
    k_main<<<148, 256, SM_TOT>>>(labels, W, leaf, out);
}

// round 10
// speedup vs baseline: 1.2613x; 1.2613x over previous
#include <cuda_runtime.h>
#include <cstdint>

#define D    512
#define NBAT 256
#define H    128
#define LDIM 64
#define NV   32000
#define G5   640          // 5*H
#define NH   (NBAT*H)     // 32768

// ---- persistent device scratch (allocation-free rule) ----
__device__ float g_hst[D * NBAT * H];     // 64 MB
__device__ float g_cst[D * NBAT * H];     // 64 MB
__device__ float g_table[(size_t)NV * G5];// 82 MB: emb@W[0:64] + b
__device__ int   g_lidx[D * NBAT];        // left-child step index, -1 = shift

__device__ __forceinline__ float sigf(float x) {
    return __fdividef(1.0f, 1.0f + __expf(-x));
}
__device__ __forceinline__ float tanhfast(float x) {
    return 1.0f - __fdividef(2.0f, __expf(2.0f * x) + 1.0f);
}
__device__ __forceinline__ float ull_lo(unsigned long long v) {
    return __uint_as_float((unsigned)(v & 0xffffffffull));
}
__device__ __forceinline__ float ull_hi(unsigned long long v) {
    return __uint_as_float((unsigned)(v >> 32));
}

// ============================================================
// K_pre: grid (1000, 5). y<4: table tiles; y==4,x==0: lidx sim.
// ============================================================
__global__ __launch_bounds__(256) void k_pre(const float* __restrict__ emb,
                                             const float* __restrict__ W,
                                             const float* __restrict__ bias,
                                             const int* __restrict__ trans) {
    if (blockIdx.y == 4) {
        if (blockIdx.x != 0) return;
        int b = threadIdx.x;
        short st[D];
        int ptr = 0;
        for (int t = 0; t < D; t++) {
            int m = trans[t * NBAT + b];
            int lx = -1;
            if (m) lx = st[ptr - 2];
            int np = ptr - 2 * m;
            st[np] = (short)t;
            ptr = np + 1;
            g_lidx[t * NBAT + b] = lx;
        }
        return;
    }
    extern __shared__ float sm[];
    float* emb_s = sm;              // [64][33]
    float* W_sc  = sm + 64 * 33;    // [64][160]
    const int v0 = blockIdx.x * 32;
    const int c0 = blockIdx.y * 160;
    const int tid = threadIdx.x;

    for (int idx = tid; idx < 32 * 64; idx += 256) {
        int vv = idx >> 6, k = idx & 63;
        emb_s[k * 33 + vv] = emb[(v0 + vv) * LDIM + k];
    }
    for (int idx = tid; idx < 64 * 40; idx += 256) {
        int k = idx / 40, cq = idx % 40;
        float4 w4 = *reinterpret_cast<const float4*>(&W[k * G5 + c0 + cq * 4]);
        *reinterpret_cast<float4*>(&W_sc[k * 160 + cq * 4]) = w4;
    }
    __syncthreads();

    const int vg = tid & 7;
    const int cg = tid >> 3;
    float acc[4][5];
#pragma unroll
    for (int j = 0; j < 5; j++) {
        float bj = __ldg(&bias[c0 + cg * 5 + j]);
#pragma unroll
        for (int i = 0; i < 4; i++) acc[i][j] = bj;
    }
#pragma unroll 4
    for (int k = 0; k < 64; k++) {
        float x[4], w[5];
#pragma unroll
        for (int i = 0; i < 4; i++) x[i] = emb_s[k * 33 + vg * 4 + i];
#pragma unroll
        for (int j = 0; j < 5; j++) w[j] = W_sc[k * 160 + cg * 5 + j];
#pragma unroll
        for (int i = 0; i < 4; i++)
#pragma unroll
            for (int j = 0; j < 5; j++) acc[i][j] += x[i] * w[j];
    }
#pragma unroll
    for (int i = 0; i < 4; i++)
#pragma unroll
        for (int j = 0; j < 5; j++)
            g_table[(size_t)(v0 + vg * 4 + i) * G5 + c0 + cg * 5 + j] = acc[i][j];
}

// ============================================================
// Main: 32 active clusters of 4 CTAs (grid 148).
// R10: register-blocked GEMM (4b x 5g per thread, 4-way k-split)
// -> LDS.128 count 3072 -> 1152 per step. W layout [jj*5+g][k].
// ============================================================
#define XK     260
#define WROW   260
#define XBUF   (8 * XK)                      // 2080 floats
#define HSROW  36
#define GPR    66                            // floats per (jj,g) row in Gp
#define SM_WT  0                             // 160*260 = 41600
#define SM_X   41600                         // + 4160 -> 45760
#define SM_GP  45760                         // 160*66 = 10560 -> 56320
#define SM_LF  56320                         // 128 -> 56448
#define SM_HS  56448                         // 288 -> 56736
#define SM_CS  56736                         // 288 -> 57024
#define SM_MB  57024                         // 8B aligned
#define SM_TOT ((57026) * 4)

__global__ __launch_bounds__(256, 1) __cluster_dims__(4, 1, 1)
void k_main(const int* __restrict__ labels,
            const float* __restrict__ W,
            const float* __restrict__ leaf,
            float* __restrict__ out) {
    const int bx = blockIdx.x;
    if ((bx >> 2) >= 32) return;   // dummy clusters

    extern __shared__ float sm[];
    float* W_T    = sm + SM_WT;    // [160 rr=jj*5+g][260]
    float* Xbuf   = sm + SM_X;     // 2 x [8][260]
    float* Gp     = sm + SM_GP;    // [160][66] partials
    float* leaf_s = sm + SM_LF;
    float* hstage = sm + SM_HS;    // [8][36]
    float* cstage = sm + SM_CS;

    const int r   = bx & 3;
    const int B   = (bx >> 2) * 8;
    const int tid = threadIdx.x;
    const int r32 = r * 32;
    const uint32_t mb = (uint32_t)__cvta_generic_to_shared(sm + SM_MB);
    const uint32_t xbase = (uint32_t)__cvta_generic_to_shared(Xbuf);

    // roles
    const int b   = tid & 7;       // nonlin batch
    const int jj  = tid >> 3;      // nonlin hdim (0..31)
    const int b2  = tid >> 5;      // cp.async / writeback batch
    const int s2  = tid & 31;      // segment / hdim col
    // GEMM roles
    const int ks  = tid >> 6;      // k-quarter 0..3
    const int w64 = tid & 63;
    const int bgq = w64 & 1;       // batch group (b = bgq*4 + i)
    const int jg  = w64 >> 1;      // GEMM hdim 0..31
    // push roles
    const int ptgt = tid >> 6;
    const int pb   = (tid & 63) >> 3;
    const int pc   = tid & 7;

    // ---- prologue: W_T[rr=jj*5+g][k] = W[64+k][g*H + r32 + jj] ----
    {
        int rr = tid < 160 ? tid : 0;
        int wjj = rr / 5, wg = rr % 5;
        for (int k = 0; k < 256; k++) {
            if (tid < 160)
                W_T[rr * WROW + k] = __ldg(&W[(64 + k) * G5 + wg * H + r32 + wjj]);
        }
    }
    if (tid < 128) leaf_s[tid] = leaf[tid];
    if (tid == 0)
        asm volatile("mbarrier.init.shared.b64 [%0], %1;" :: "r"(mb), "r"(4) : "memory");
    __syncthreads();
    asm volatile("barrier.cluster.arrive.aligned;" ::: "memory");
    asm volatile("barrier.cluster.wait.aligned;" ::: "memory");

    // leafW for nonlin roles (b, jj)
    float lw5[5];
#pragma unroll
    for (int g = 0; g < 5; g++) lw5[g] = 0.0f;
    for (int k = 0; k < 128; k++) {
        float lv = leaf_s[k];
#pragma unroll
        for (int g = 0; g < 5; g++)
            lw5[g] += lv * (W_T[(jj * 5 + g) * WROW + k]
                          + W_T[(jj * 5 + g) * WROW + 128 + k]);
    }

    // schedule regs
    int liA  = __ldg(&g_lidx[B + b]);
    int liB  = __ldg(&g_lidx[NBAT + B + b]);
    int labB = __ldg(&labels[NBAT + B + b]);
    float tab5[5];
    {
        int labA = __ldg(&labels[B + b]);
#pragma unroll
        for (int g = 0; g < 5; g++)
            tab5[g] = __ldg(&g_table[(size_t)labA * G5 + g * H + r32 + jj]);
    }
    float cl = leaf_s[r32 + jj];
    float cprev = 0.0f;
    int cur = 0;

    for (int t = 0; t < D; t++) {
        __syncthreads();   // X[cur] complete
        float* Xc = Xbuf + cur * XBUF;
        const int nxt = cur ^ 1;

        float cln = 0.0f, t5n[5];
        int liC = 0, labC = 0;
        if (t < D - 1) {
            bool redB = (liB >= 0);
            cln = redB
                ? ((liB == t - 1) ? cprev
                   : __ldcg(&g_cst[(size_t)liB * NH + (B + b) * H + r32 + jj]))
                : leaf_s[r32 + jj];
#pragma unroll
            for (int g = 0; g < 5; g++)
                t5n[g] = __ldg(&g_table[(size_t)labB * G5 + g * H + r32 + jj]);
            const int t2 = (t + 2 < D) ? (t + 2) : (D - 1);
            liC  = __ldg(&g_lidx[t2 * NBAT + B + b]);
            labC = __ldg(&labels[t2 * NBAT + B + b]);

            // left-half X[next]
            int li2 = __ldg(&g_lidx[(t + 1) * NBAT + B + b2]);
            if (li2 >= 0) {
                uint32_t dst = xbase + (nxt * XBUF + b2 * XK + s2 * 4) * 4;
                if (li2 == t - 1) {
                    float4 v = *reinterpret_cast<const float4*>(
                        &Xc[b2 * XK + 128 + s2 * 4]);
                    *reinterpret_cast<float4*>(
                        &Xbuf[nxt * XBUF + b2 * XK + s2 * 4]) = v;
                } else {
                    const float* src = &g_hst[(size_t)li2 * NH + (B + b2) * H + s2 * 4];
                    asm volatile("cp.async.cg.shared.global [%0], [%1], 16;"
                                 :: "r"(dst), "l"(src) : "memory");
                }
            }
            asm volatile("cp.async.commit_group;" ::: "memory");
        }

        // ---- GEMM: thread (ks, bgq, jg): 4 batches x 5 gates, K/4 ----
        unsigned long long acc[4][5];
#pragma unroll
        for (int i = 0; i < 4; i++)
#pragma unroll
            for (int g = 0; g < 5; g++) acc[i][g] = 0ULL;
        {
            const float* xb0 = Xc + (bgq * 4) * XK + ks * 64;
            const ulonglong2* wp =
                reinterpret_cast<const ulonglong2*>(W_T + (jg * 5) * WROW + ks * 64);
#pragma unroll 4
            for (int p = 0; p < 16; p++) {
                ulonglong2 xv[4];
#pragma unroll
                for (int i = 0; i < 4; i++)
                    xv[i] = *reinterpret_cast<const ulonglong2*>(xb0 + i * XK + p * 4);
#pragma unroll
                for (int g = 0; g < 5; g++) {
                    ulonglong2 wv = wp[g * 65 + p];   // g stride = WROW floats
#pragma unroll
                    for (int i = 0; i < 4; i++) {
                        asm("fma.rn.f32x2 %0, %1, %2, %0;"
                            : "+l"(acc[i][g]) : "l"(xv[i].x), "l"(wv.x));
                        asm("fma.rn.f32x2 %0, %1, %2, %0;"
                            : "+l"(acc[i][g]) : "l"(xv[i].y), "l"(wv.y));
                    }
                }
            }
        }
        // partials -> Gp[(jg*5+g)*GPR + ks*16 + b*2]
#pragma unroll
        for (int g = 0; g < 5; g++)
#pragma unroll
            for (int i = 0; i < 4; i++)
                *reinterpret_cast<unsigned long long*>(
                    &Gp[(jg * 5 + g) * GPR + ks * 16 + (bgq * 4 + i) * 2]) = acc[i][g];
        __syncthreads();

        // ---- reduce + nonlinearity: thread owns (b, jj) ----
        {
            float gate[5];
            if (liA >= 0) {
#pragma unroll
                for (int g = 0; g < 5; g++) {
                    float s = tab5[g];
#pragma unroll
                    for (int q2 = 0; q2 < 4; q2++) {
                        unsigned long long pv = *reinterpret_cast<unsigned long long*>(
                            &Gp[(jj * 5 + g) * GPR + q2 * 16 + b * 2]);
                        s += ull_lo(pv) + ull_hi(pv);
                    }
                    gate[g] = s;
                }
            } else {
#pragma unroll
                for (int g = 0; g < 5; g++) gate[g] = tab5[g] + lw5[g];
            }
            float lf  = leaf_s[r32 + jj];
            float clv = (liA >= 0) ? cl    : lf;
            float crv = (liA >= 0) ? cprev : lf;
            float c = sigf(gate[0]) * tanhfast(gate[4])
                    + sigf(gate[1]) * clv + sigf(gate[2]) * crv;
            float h = sigf(gate[3]) * tanhfast(c);
            cprev = c;
            hstage[b * HSROW + jj] = h;
            cstage[b * HSROW + jj] = c;
        }
        __syncthreads();   // stage complete

        // ---- coalesced v4 push ----
        if (t < D - 1) {
            float4 v = *reinterpret_cast<const float4*>(&hstage[pb * HSROW + pc * 4]);
            uint32_t xaddr = xbase + (nxt * XBUF + pb * XK + 128 + r32 + pc * 4) * 4;
            if (ptgt == r) {
                *reinterpret_cast<float4*>(
                    &Xbuf[nxt * XBUF + pb * XK + 128 + r32 + pc * 4]) = v;
            } else {
                uint32_t rem;
                asm("mapa.shared::cluster.u32 %0, %1, %2;"
                    : "=r"(rem) : "r"(xaddr), "r"(ptgt));
                asm volatile("st.shared::cluster.v4.f32 [%0], {%1, %2, %3, %4};"
                             :: "r"(rem), "f"(v.x), "f"(v.y), "f"(v.z), "f"(v.w)
                             : "memory");
            }
        }
        // ---- writeback BEFORE arrive ----
        {
            float hv = hstage[b2 * HSROW + s2];
            float cv = cstage[b2 * HSROW + s2];
            const size_t o = (size_t)t * NH + (B + b2) * H + r32 + s2;
            __stcg(&g_hst[o], hv);
            __stcg(&g_cst[o], cv);
            if (t == D - 1) {
                out[(B + b2) * H + r32 + s2]      = cv;   // cells
                out[NH + (B + b2) * H + r32 + s2] = hv;   // embeddings
            }
        }
        __syncthreads();

        // ---- handshake ----
        if (t < D - 1) {
            if (tid < 4) {
                uint32_t rem;
                asm("mapa.shared::cluster.u32 %0, %1, %2;"
                    : "=r"(rem) : "r"(mb), "r"(tid));
                asm volatile("mbarrier.arrive.release.cluster.shared::cluster.b64 _, [%0];"
                             :: "r"(rem) : "memory");
            }
            const unsigned par = t & 1;
            asm volatile(
                "{\n\t"
                ".reg .pred P;\n\t"
                "WL%=:\n\t"
                "mbarrier.try_wait.parity.acquire.cluster.shared::cta.b64 P, [%0], %1, 0x989680;\n\t"
                "@P bra WD%=;\n\t"
                "bra WL%=;\n\t"
                "WD%=:\n\t"
                "}" :: "r"(mb), "r"(par) : "memory");
            asm volatile("cp.async.wait_group 0;" ::: "memory");
        }

        liA = liB; liB = liC; labB = labC;
        cl = cln;
#pragma unroll
        for (int g = 0; g < 5; g++) tab5[g] = t5n[g];
        cur ^= 1;
    }

    asm volatile("barrier.cluster.arrive.aligned;" ::: "memory");
    asm volatile("barrier.cluster.wait.aligned;" ::: "memory");
}

// ============================================================
extern "C" void kernel_launch(void* const* d_in, const int* in_sizes, int n_in,
                              void* d_out, int out_size) {
    const int*   trans  = (const int*)d_in[0];
    const int*   labels = (const int*)d_in[1];
    const float* emb    = (const float*)d_in[2];
    const float* W      = (const float*)d_in[3];
    const float* bias   = (const float*)d_in[4];
    const float* leaf   = (const float*)d_in[5];
    float* out = (float*)d_out;

    cudaFuncSetAttribute(k_pre, cudaFuncAttributeMaxDynamicSharedMemorySize,
                         64 * 33 * 4 + 64 * 160 * 4);
    cudaFuncSetAttribute(k_main, cudaFuncAttributeMaxDynamicSharedMemorySize,
                         SM_TOT);

    dim3 pgrid(NV / 32, 5);
    k_pre<<<pgrid, 256, 64 * 33 * 4 + 64 * 160 * 4>>>(emb, W, bias, trans);
    k_main<<<148, 256, SM_TOT>>>(labels, W, leaf, out);
}

// round 11
// speedup vs baseline: 1.5605x; 1.2372x over previous
#include <cuda_runtime.h>
#include <cstdint>

#define D    512
#define NBAT 256
#define H    128
#define LDIM 64
#define NV   32000
#define G5   640          // 5*H
#define NH   (NBAT*H)     // 32768

// ---- persistent device scratch (allocation-free rule) ----
__device__ float g_hst[D * NBAT * H];     // 64 MB
__device__ float g_cst[D * NBAT * H];     // 64 MB
__device__ float g_table[(size_t)NV * G5];// 82 MB: emb@W[0:64] + b
__device__ int   g_lidx[D * NBAT];        // left-child step index, -1 = shift

__device__ __forceinline__ float sigf(float x) {
    return __fdividef(1.0f, 1.0f + __expf(-x));
}
__device__ __forceinline__ float tanhfast(float x) {
    return 1.0f - __fdividef(2.0f, __expf(2.0f * x) + 1.0f);
}
__device__ __forceinline__ float ull_lo(unsigned long long v) {
    return __uint_as_float((unsigned)(v & 0xffffffffull));
}
__device__ __forceinline__ float ull_hi(unsigned long long v) {
    return __uint_as_float((unsigned)(v >> 32));
}

// ============================================================
// K_pre: grid (1000, 5). y<4: table tiles; y==4,x==0: lidx sim.
// ============================================================
__global__ __launch_bounds__(256) void k_pre(const float* __restrict__ emb,
                                             const float* __restrict__ W,
                                             const float* __restrict__ bias,
                                             const int* __restrict__ trans) {
    if (blockIdx.y == 4) {
        if (blockIdx.x != 0) return;
        int b = threadIdx.x;
        short st[D];
        int ptr = 0;
        for (int t = 0; t < D; t++) {
            int m = trans[t * NBAT + b];
            int lx = -1;
            if (m) lx = st[ptr - 2];
            int np = ptr - 2 * m;
            st[np] = (short)t;
            ptr = np + 1;
            g_lidx[t * NBAT + b] = lx;
        }
        return;
    }
    extern __shared__ float sm[];
    float* emb_s = sm;              // [64][33]
    float* W_sc  = sm + 64 * 33;    // [64][160]
    const int v0 = blockIdx.x * 32;
    const int c0 = blockIdx.y * 160;
    const int tid = threadIdx.x;

    for (int idx = tid; idx < 32 * 64; idx += 256) {
        int vv = idx >> 6, k = idx & 63;
        emb_s[k * 33 + vv] = emb[(v0 + vv) * LDIM + k];
    }
    for (int idx = tid; idx < 64 * 40; idx += 256) {
        int k = idx / 40, cq = idx % 40;
        float4 w4 = *reinterpret_cast<const float4*>(&W[k * G5 + c0 + cq * 4]);
        *reinterpret_cast<float4*>(&W_sc[k * 160 + cq * 4]) = w4;
    }
    __syncthreads();

    const int vg = tid & 7;
    const int cg = tid >> 3;
    float acc[4][5];
#pragma unroll
    for (int j = 0; j < 5; j++) {
        float bj = __ldg(&bias[c0 + cg * 5 + j]);
#pragma unroll
        for (int i = 0; i < 4; i++) acc[i][j] = bj;
    }
#pragma unroll 4
    for (int k = 0; k < 64; k++) {
        float x[4], w[5];
#pragma unroll
        for (int i = 0; i < 4; i++) x[i] = emb_s[k * 33 + vg * 4 + i];
#pragma unroll
        for (int j = 0; j < 5; j++) w[j] = W_sc[k * 160 + cg * 5 + j];
#pragma unroll
        for (int i = 0; i < 4; i++)
#pragma unroll
            for (int j = 0; j < 5; j++) acc[i][j] += x[i] * w[j];
    }
#pragma unroll
    for (int i = 0; i < 4; i++)
#pragma unroll
        for (int j = 0; j < 5; j++)
            g_table[(size_t)(v0 + vg * 4 + i) * G5 + c0 + cg * 5 + j] = acc[i][j];
}

// ============================================================
// Main: 32 active clusters of 4 CTAs (grid 148).
// R11: GEMM split k<128 / k>=128; handshake wait deferred between
// the halves so left-GEMM hides fabric latency + sibling skew.
// 3 syncthreads/step (top sync removed).
// ============================================================
#define XK     260
#define WROW   260
#define XBUF   (8 * XK)                      // 2080 floats
#define HSROW  36
#define GPR    66
#define SM_WT  0                             // 160*260 = 41600
#define SM_X   41600                         // + 4160 -> 45760
#define SM_GP  45760                         // 160*66 = 10560 -> 56320
#define SM_LF  56320                         // 128 -> 56448
#define SM_HS  56448                         // 288 -> 56736
#define SM_CS  56736                         // 288 -> 57024
#define SM_MB  57024                         // 8B aligned
#define SM_TOT ((57026) * 4)

__global__ __launch_bounds__(256, 1) __cluster_dims__(4, 1, 1)
void k_main(const int* __restrict__ labels,
            const float* __restrict__ W,
            const float* __restrict__ leaf,
            float* __restrict__ out) {
    const int bx = blockIdx.x;
    if ((bx >> 2) >= 32) return;   // dummy clusters

    extern __shared__ float sm[];
    float* W_T    = sm + SM_WT;    // [160 rr=jj*5+g][260]
    float* Xbuf   = sm + SM_X;     // 2 x [8][260]
    float* Gp     = sm + SM_GP;    // [160][66]
    float* leaf_s = sm + SM_LF;
    float* hstage = sm + SM_HS;    // [8][36]
    float* cstage = sm + SM_CS;

    const int r   = bx & 3;
    const int B   = (bx >> 2) * 8;
    const int tid = threadIdx.x;
    const int r32 = r * 32;
    const uint32_t mb = (uint32_t)__cvta_generic_to_shared(sm + SM_MB);
    const uint32_t xbase = (uint32_t)__cvta_generic_to_shared(Xbuf);

    // roles
    const int b   = tid & 7;       // nonlin batch
    const int jj  = tid >> 3;      // nonlin hdim
    const int b2  = tid >> 5;      // cp.async / writeback batch
    const int s2  = tid & 31;
    // GEMM roles
    const int ks  = tid >> 6;      // k-quarter 0..3 (0,1: left; 2,3: right)
    const int w64 = tid & 63;
    const int bgq = w64 & 1;
    const int jg  = w64 >> 1;
    // push roles
    const int ptgt = tid >> 6;
    const int pb   = (tid & 63) >> 3;
    const int pc   = tid & 7;

    // ---- prologue: W_T[rr=jj*5+g][k] = W[64+k][g*H + r32 + jj] ----
    {
        int rr = tid < 160 ? tid : 0;
        int wjj = rr / 5, wg = rr % 5;
        for (int k = 0; k < 256; k++) {
            if (tid < 160)
                W_T[rr * WROW + k] = __ldg(&W[(64 + k) * G5 + wg * H + r32 + wjj]);
        }
    }
    if (tid < 128) leaf_s[tid] = leaf[tid];
    if (tid == 0)
        asm volatile("mbarrier.init.shared.b64 [%0], %1;" :: "r"(mb), "r"(4) : "memory");
    __syncthreads();
    asm volatile("barrier.cluster.arrive.aligned;" ::: "memory");
    asm volatile("barrier.cluster.wait.aligned;" ::: "memory");

    // leafW for nonlin roles (b, jj)
    float lw5[5];
#pragma unroll
    for (int g = 0; g < 5; g++) lw5[g] = 0.0f;
    for (int k = 0; k < 128; k++) {
        float lv = leaf_s[k];
#pragma unroll
        for (int g = 0; g < 5; g++)
            lw5[g] += lv * (W_T[(jj * 5 + g) * WROW + k]
                          + W_T[(jj * 5 + g) * WROW + 128 + k]);
    }

    // schedule regs
    int liA  = __ldg(&g_lidx[B + b]);
    int liB  = __ldg(&g_lidx[NBAT + B + b]);
    int labB = __ldg(&labels[NBAT + B + b]);
    float tab5[5];
    {
        int labA = __ldg(&labels[B + b]);
#pragma unroll
        for (int g = 0; g < 5; g++)
            tab5[g] = __ldg(&g_table[(size_t)labA * G5 + g * H + r32 + jj]);
    }
    float cl = leaf_s[r32 + jj];
    float cprev = 0.0f;
    int cur = 0;

    for (int t = 0; t < D; t++) {
        float* Xc = Xbuf + cur * XBUF;
        const int nxt = cur ^ 1;

        float cln = 0.0f, t5n[5];
        int liC = 0, labC = 0;
        int li2 = -1;
        if (t < D - 1) {
            bool redB = (liB >= 0);
            cln = redB
                ? ((liB == t - 1) ? cprev
                   : __ldcg(&g_cst[(size_t)liB * NH + (B + b) * H + r32 + jj]))
                : leaf_s[r32 + jj];
#pragma unroll
            for (int g = 0; g < 5; g++)
                t5n[g] = __ldg(&g_table[(size_t)labB * G5 + g * H + r32 + jj]);
            const int t2 = (t + 2 < D) ? (t + 2) : (D - 1);
            liC  = __ldg(&g_lidx[t2 * NBAT + B + b]);
            labC = __ldg(&labels[t2 * NBAT + B + b]);

            // cp.async for X[next] left (global path only; li2==t-1 deferred)
            li2 = __ldg(&g_lidx[(t + 1) * NBAT + B + b2]);
            if (li2 >= 0 && li2 != t - 1) {
                uint32_t dst = xbase + (nxt * XBUF + b2 * XK + s2 * 4) * 4;
                const float* src = &g_hst[(size_t)li2 * NH + (B + b2) * H + s2 * 4];
                asm volatile("cp.async.cg.shared.global [%0], [%1], 16;"
                             :: "r"(dst), "l"(src) : "memory");
            }
            asm volatile("cp.async.commit_group;" ::: "memory");
        }

        // ---- GEMM accumulators ----
        unsigned long long acc[4][5];
#pragma unroll
        for (int i = 0; i < 4; i++)
#pragma unroll
            for (int g = 0; g < 5; g++) acc[i][g] = 0ULL;

        const float* xb0 = Xc + (bgq * 4) * XK + ks * 64;
        const ulonglong2* wp =
            reinterpret_cast<const ulonglong2*>(W_T + (jg * 5) * WROW + ks * 64);

        // ---- LEFT half first for ks<2 (k<128): valid at loop top ----
        if (ks < 2) {
#pragma unroll 4
            for (int p = 0; p < 16; p++) {
                ulonglong2 xv[4];
#pragma unroll
                for (int i = 0; i < 4; i++)
                    xv[i] = *reinterpret_cast<const ulonglong2*>(xb0 + i * XK + p * 4);
#pragma unroll
                for (int g = 0; g < 5; g++) {
                    ulonglong2 wv = wp[g * 65 + p];
#pragma unroll
                    for (int i = 0; i < 4; i++) {
                        asm("fma.rn.f32x2 %0, %1, %2, %0;"
                            : "+l"(acc[i][g]) : "l"(xv[i].x), "l"(wv.x));
                        asm("fma.rn.f32x2 %0, %1, %2, %0;"
                            : "+l"(acc[i][g]) : "l"(xv[i].y), "l"(wv.y));
                    }
                }
            }
        }

        // ---- deferred handshake wait (h_{t-1}): protects X[cur] right ----
        if (t > 0) {
            const unsigned par = (t - 1) & 1;
            asm volatile(
                "{\n\t"
                ".reg .pred P;\n\t"
                "WL%=:\n\t"
                "mbarrier.try_wait.parity.acquire.cluster.shared::cta.b64 P, [%0], %1, 0x989680;\n\t"
                "@P bra WD%=;\n\t"
                "bra WL%=;\n\t"
                "WD%=:\n\t"
                "}" :: "r"(mb), "r"(par) : "memory");
        }

        // local copy: X[next] left <- X[cur] right (left child == t-1)
        if (li2 == t - 1 && li2 >= 0) {
            float4 v = *reinterpret_cast<const float4*>(&Xc[b2 * XK + 128 + s2 * 4]);
            *reinterpret_cast<float4*>(&Xbuf[nxt * XBUF + b2 * XK + s2 * 4]) = v;
        }

        // ---- RIGHT half for ks>=2 (k>=128): needs pushes of h(t-1) ----
        if (ks >= 2) {
#pragma unroll 4
            for (int p = 0; p < 16; p++) {
                ulonglong2 xv[4];
#pragma unroll
                for (int i = 0; i < 4; i++)
                    xv[i] = *reinterpret_cast<const ulonglong2*>(xb0 + i * XK + p * 4);
#pragma unroll
                for (int g = 0; g < 5; g++) {
                    ulonglong2 wv = wp[g * 65 + p];
#pragma unroll
                    for (int i = 0; i < 4; i++) {
                        asm("fma.rn.f32x2 %0, %1, %2, %0;"
                            : "+l"(acc[i][g]) : "l"(xv[i].x), "l"(wv.x));
                        asm("fma.rn.f32x2 %0, %1, %2, %0;"
                            : "+l"(acc[i][g]) : "l"(xv[i].y), "l"(wv.y));
                    }
                }
            }
        }

        // partials -> Gp
#pragma unroll
        for (int g = 0; g < 5; g++)
#pragma unroll
            for (int i = 0; i < 4; i++)
                *reinterpret_cast<unsigned long long*>(
                    &Gp[(jg * 5 + g) * GPR + ks * 16 + (bgq * 4 + i) * 2]) = acc[i][g];
        __syncthreads();   // (1)

        // ---- reduce + nonlinearity: thread owns (b, jj) ----
        {
            float gate[5];
            if (liA >= 0) {
#pragma unroll
                for (int g = 0; g < 5; g++) {
                    float s = tab5[g];
#pragma unroll
                    for (int q2 = 0; q2 < 4; q2++) {
                        unsigned long long pv = *reinterpret_cast<unsigned long long*>(
                            &Gp[(jj * 5 + g) * GPR + q2 * 16 + b * 2]);
                        s += ull_lo(pv) + ull_hi(pv);
                    }
                    gate[g] = s;
                }
            } else {
#pragma unroll
                for (int g = 0; g < 5; g++) gate[g] = tab5[g] + lw5[g];
            }
            float lf  = leaf_s[r32 + jj];
            float clv = (liA >= 0) ? cl    : lf;
            float crv = (liA >= 0) ? cprev : lf;
            float c = sigf(gate[0]) * tanhfast(gate[4])
                    + sigf(gate[1]) * clv + sigf(gate[2]) * crv;
            float h = sigf(gate[3]) * tanhfast(c);
            cprev = c;
            hstage[b * HSROW + jj] = h;
            cstage[b * HSROW + jj] = c;
        }
        __syncthreads();   // (2)

        // ---- coalesced v4 push into X[next] right ----
        if (t < D - 1) {
            float4 v = *reinterpret_cast<const float4*>(&hstage[pb * HSROW + pc * 4]);
            uint32_t xaddr = xbase + (nxt * XBUF + pb * XK + 128 + r32 + pc * 4) * 4;
            if (ptgt == r) {
                *reinterpret_cast<float4*>(
                    &Xbuf[nxt * XBUF + pb * XK + 128 + r32 + pc * 4]) = v;
            } else {
                uint32_t rem;
                asm("mapa.shared::cluster.u32 %0, %1, %2;"
                    : "=r"(rem) : "r"(xaddr), "r"(ptgt));
                asm volatile("st.shared::cluster.v4.f32 [%0], {%1, %2, %3, %4};"
                             :: "r"(rem), "f"(v.x), "f"(v.y), "f"(v.z), "f"(v.w)
                             : "memory");
            }
        }
        // ---- writeback BEFORE arrive ----
        {
            float hv = hstage[b2 * HSROW + s2];
            float cv = cstage[b2 * HSROW + s2];
            const size_t o = (size_t)t * NH + (B + b2) * H + r32 + s2;
            __stcg(&g_hst[o], hv);
            __stcg(&g_cst[o], cv);
            if (t == D - 1) {
                out[(B + b2) * H + r32 + s2]      = cv;   // cells
                out[NH + (B + b2) * H + r32 + s2] = hv;   // embeddings
            }
        }
        __syncthreads();   // (3)

        // ---- release arrive (wait is deferred into next step) ----
        if (t < D - 1) {
            if (tid < 4) {
                uint32_t rem;
                asm("mapa.shared::cluster.u32 %0, %1, %2;"
                    : "=r"(rem) : "r"(mb), "r"(tid));
                asm volatile("mbarrier.arrive.release.cluster.shared::cluster.b64 _, [%0];"
                             :: "r"(rem) : "memory");
            }
            asm volatile("cp.async.wait_group 0;" ::: "memory");
        }

        liA = liB; liB = liC; labB = labC;
        cl = cln;
#pragma unroll
        for (int g = 0; g < 5; g++) tab5[g] = t5n[g];
        cur ^= 1;
    }

    asm volatile("barrier.cluster.arrive.aligned;" ::: "memory");
    asm volatile("barrier.cluster.wait.aligned;" ::: "memory");
}

// ============================================================
extern "C" void kernel_launch(void* const* d_in, const int* in_sizes, int n_in,
                              void* d_out, int out_size) {
    const int*   trans  = (const int*)d_in[0];
    const int*   labels = (const int*)d_in[1];
    const float* emb    = (const float*)d_in[2];
    const float* W      = (const float*)d_in[3];
    const float* bias   = (const float*)d_in[4];
    const float* leaf   = (const float*)d_in[5];
    float* out = (float*)d_out;

    cudaFuncSetAttribute(k_pre, cudaFuncAttributeMaxDynamicSharedMemorySize,
                         64 * 33 * 4 + 64 * 160 * 4);
    cudaFuncSetAttribute(k_main, cudaFuncAttributeMaxDynamicSharedMemorySize,
                         SM_TOT);

    dim3 pgrid(NV / 32, 5);
    k_pre<<<pgrid, 256, 64 * 33 * 4 + 64 * 160 * 4>>>(emb, W, bias, trans);
    k_main<<<148, 256, SM_TOT>>>(labels, W, leaf, out);
}